// round 15
// baseline (speedup 1.0000x reference)
#include <cuda_runtime.h>
#include <math.h>

#define HDIM 128
#define LLAYERS 5
#define NMAX 100000
#define EMAX 200000
#define GMAX 2000

// packed (bf16x2) smem strides in u32 units
#define SA_LAYER 68   // 64 data + 4 pad
#define SA_NODE  20   // 16 data + 4 pad

// ---------------- scratch (static device globals; no allocation) ----------------
__device__ float    g_h[NMAX * HDIM];     // h ping
__device__ float    g_hb[NMAX * HDIM];    // h pong
__device__ float    g_etab[LLAYERS * 24 * HDIM];
__device__ __align__(16) unsigned g_wfrag[368640];   // bf16 hi/lo weight fragments
// CSR-by-dst scratch
__device__ int      g_deg[NMAX];
__device__ int      g_rowincl[NMAX];
__device__ int      g_rowoff[NMAX + 1];
__device__ int      g_cur[NMAX];
__device__ int      g_part[256];
__device__ unsigned g_edt[EMAX];          // src | type<<20
// head scratch
__device__ float    g_gemb[GMAX * 256];
__device__ float    g_ex1[GMAX * HDIM];
__device__ float    g_ex2[GMAX * HDIM];
__device__ float    g_comb[GMAX * 384];
__device__ float    g_o1[GMAX * 256];
__device__ float    g_o2[GMAX * 128];

// ---------------- helpers ----------------
__device__ __forceinline__ void bf16_split2(float x, float y, unsigned& hi, unsigned& lo) {
    asm("cvt.rn.bf16x2.f32 %0, %1, %2;" : "=r"(hi) : "f"(y), "f"(x));
    float hx = __uint_as_float(hi << 16);
    float hy = __uint_as_float(hi & 0xffff0000u);
    float lx = x - hx, ly = y - hy;
    asm("cvt.rn.bf16x2.f32 %0, %1, %2;" : "=r"(lo) : "f"(ly), "f"(lx));
}
__device__ __forceinline__ void mma_bf16(float c[4], const unsigned a[4],
                                         unsigned b0, unsigned b1) {
    asm volatile(
        "mma.sync.aligned.m16n8k16.row.col.f32.bf16.bf16.f32 "
        "{%0,%1,%2,%3}, {%4,%5,%6,%7}, {%8,%9}, {%0,%1,%2,%3};"
        : "+f"(c[0]), "+f"(c[1]), "+f"(c[2]), "+f"(c[3])
        : "r"(a[0]), "r"(a[1]), "r"(a[2]), "r"(a[3]), "r"(b0), "r"(b1));
}
__device__ __forceinline__ unsigned smaddr(const void* p) {
    return (unsigned)__cvta_generic_to_shared(p);
}
__device__ __forceinline__ void ldsm_x4(unsigned a[4], unsigned addr) {
    asm volatile("ldmatrix.sync.aligned.m8n8.x4.shared.b16 {%0,%1,%2,%3}, [%4];"
                 : "=r"(a[0]), "=r"(a[1]), "=r"(a[2]), "=r"(a[3]) : "r"(addr));
}

// ---------------- weight fragment precompute (bf16 hi/lo split, batched) --------
__global__ void wfrag_batch_kernel(const float* __restrict__ W, unsigned* __restrict__ out,
                                   int wstride, int ostride)
{
    const float* Wm = W + (size_t)blockIdx.z * wstride;
    unsigned* om = out + (size_t)blockIdx.z * ostride;
    int ks = blockIdx.x, nt = blockIdx.y, lane = threadIdx.x;
    int n  = nt * 8 + (lane >> 2);
    int k0 = ks * 16 + (lane & 3) * 2;
    float w00 = Wm[k0 * 128 + n];
    float w01 = Wm[(k0 + 1) * 128 + n];
    float w10 = Wm[(k0 + 8) * 128 + n];
    float w11 = Wm[(k0 + 9) * 128 + n];
    unsigned bh0, bl0, bh1, bl1;
    bf16_split2(w00, w01, bh0, bl0);
    bf16_split2(w10, w11, bh1, bl1);
    unsigned* p = om + ((size_t)(ks * 16 + nt) * 32 + lane) * 4;
    p[0] = bh0; p[1] = bh1; p[2] = bl0; p[3] = bl1;
}

// ---------------- 3x-bf16 tile GEMM: ldmatrix A + cp.async-staged B frags -------
template <int K, int SA>
__device__ __forceinline__ void gemm_tile_ldm(const unsigned* Ahi, const unsigned* Alo,
                                              const unsigned* __restrict__ frag,
                                              unsigned* FragS, int tid,
                                              int rowgrp, int colgrp, int lane,
                                              float acc[2][8][4])
{
    const int NKS = K / 16;
    const int lrow = lane & 15;
    const int lcol = (lane >> 4) * 4;

    // preload ks=0 fragment chunk (8KB = 256 threads x 2 x 16B)
    {
        unsigned daddr = smaddr(FragS) + tid * 16;
        const unsigned* src = frag + tid * 4;
        asm volatile(
            "cp.async.ca.shared.global [%0], [%1], 16;\n\t"
            "cp.async.ca.shared.global [%2], [%3], 16;\n\t"
            "cp.async.commit_group;"
            :: "r"(daddr), "l"(src), "r"(daddr + 4096), "l"(src + 1024) : "memory");
    }

    #pragma unroll
    for (int ks = 0; ks < NKS; ks++) {
        const unsigned* cur = FragS + (ks & 1) * 2048;
        asm volatile("cp.async.wait_group 0;" ::: "memory");
        __syncthreads();
        if (ks + 1 < NKS) {
            unsigned daddr = smaddr(FragS + ((ks + 1) & 1) * 2048) + tid * 16;
            const unsigned* src = frag + (size_t)(ks + 1) * 2048 + tid * 4;
            asm volatile(
                "cp.async.ca.shared.global [%0], [%1], 16;\n\t"
                "cp.async.ca.shared.global [%2], [%3], 16;\n\t"
                "cp.async.commit_group;"
                :: "r"(daddr), "l"(src), "r"(daddr + 4096), "l"(src + 1024) : "memory");
        }
        unsigned ahi[2][4], alo[2][4];
        #pragma unroll
        for (int mt = 0; mt < 2; mt++) {
            int row = rowgrp * 32 + mt * 16 + lrow;
            unsigned off = 4u * (row * SA + ks * 8 + lcol);
            ldsm_x4(ahi[mt], smaddr(Ahi) + off);
            ldsm_x4(alo[mt], smaddr(Alo) + off);
        }
        #pragma unroll
        for (int t = 0; t < 8; t++) {
            const uint4 bf = *(const uint4*)(cur + ((colgrp * 8 + t) * 32 + lane) * 4);
            #pragma unroll
            for (int mt = 0; mt < 2; mt++) {
                mma_bf16(acc[mt][t], ahi[mt], bf.x, bf.y);   // hi*hi
                mma_bf16(acc[mt][t], ahi[mt], bf.z, bf.w);   // hi*lo
                mma_bf16(acc[mt][t], alo[mt], bf.x, bf.y);   // lo*hi
            }
        }
    }
}

// ---------------- fused gather + 2-GEMM MLP ----------------
// LAYER=true : A_in[r] = A[r] + sum_{e in CSR[r]} relu(A[src_e] + etab[type_e]);
//              Hout[r] = relu(bn(mlp(A_in))) + A[r]
// LAYER=false: Hout[r] = mlp(A)   (A = x, K1=32)
template <int K1, bool LAYER>
__global__ __launch_bounds__(256, 2)
void mlp2_mma_kernel(const float* __restrict__ A, int N,
                     const unsigned* __restrict__ frag1, const float* __restrict__ b1,
                     const unsigned* __restrict__ frag2, const float* __restrict__ b2,
                     const float* __restrict__ gamma, const float* __restrict__ beta,
                     float bnscale, float* __restrict__ Hout,
                     const float* __restrict__ etab_l,
                     const int* __restrict__ rowoff, const unsigned* __restrict__ edt)
{
    extern __shared__ unsigned smu[];
    unsigned* Ahi   = smu;
    unsigned* Alo   = smu + 128 * SA_LAYER;
    unsigned* FragS = smu + 2 * 128 * SA_LAYER;   // 4096 u32 double buffer
    const int tid = threadIdx.x, lane = tid & 31, warp = tid >> 5;
    const int rowgrp = warp >> 1, colgrp = warp & 1;
    const int n0 = blockIdx.x * 128;

    if (LAYER) {
        // -- staged gather: batch the CSR dependency levels through smem --
        int*      sro = (int*)FragS;       // rowoff[n0 .. n0+128]  (129 ints)
        unsigned* sed = FragS + 132;       // block's contiguous edge span
        const int SEDCAP = 4096 - 132;
        for (int i = tid; i < 129; i += 256) {
            int rr = n0 + i; if (rr > N) rr = N;
            sro[i] = __ldg(rowoff + rr);
        }
        __syncthreads();
        const int eb = sro[0];
        const int ned = sro[128] - eb;
        const bool staged = (ned <= SEDCAP);
        if (staged) {
            for (int i = tid; i < ned; i += 256)
                sed[i] = __ldg(edt + eb + i);
        }
        __syncthreads();

        for (int r = warp; r < 128; r += 8) {
            int row = n0 + r;
            float4 a = make_float4(0.f, 0.f, 0.f, 0.f);
            if (row < N) {
                a = *(const float4*)(A + (size_t)row * 128 + lane * 4);
                int e0 = sro[r], e1 = sro[r + 1];
                for (int e = e0; e < e1; e++) {
                    unsigned pk = staged ? sed[e - eb] : __ldg(edt + e);
                    const float* hv = A + (size_t)(pk & 0xFFFFF) * 128;
                    const float* et = etab_l + (pk >> 20) * 128;
                    float4 h4 = *(const float4*)(hv + lane * 4);
                    float4 e4 = *(const float4*)(et + lane * 4);
                    a.x += fmaxf(h4.x + e4.x, 0.f);
                    a.y += fmaxf(h4.y + e4.y, 0.f);
                    a.z += fmaxf(h4.z + e4.z, 0.f);
                    a.w += fmaxf(h4.w + e4.w, 0.f);
                }
            }
            unsigned h0, l0, h1, l1;
            bf16_split2(a.x, a.y, h0, l0);
            bf16_split2(a.z, a.w, h1, l1);
            *(uint2*)(Ahi + r * SA_LAYER + lane * 2) = make_uint2(h0, h1);
            *(uint2*)(Alo + r * SA_LAYER + lane * 2) = make_uint2(l0, l1);
        }
    } else {
        const int QK = K1 / 4;
        #pragma unroll
        for (int i = 0; i < (128 * QK) / 256; i++) {
            int idx = tid + i * 256;
            int r = idx / QK, cq = idx % QK;
            float4 v = make_float4(0.f, 0.f, 0.f, 0.f);
            if (n0 + r < N)
                v = *(const float4*)(A + (size_t)(n0 + r) * K1 + cq * 4);
            unsigned h0, l0, h1, l1;
            bf16_split2(v.x, v.y, h0, l0);
            bf16_split2(v.z, v.w, h1, l1);
            *(uint2*)(Ahi + r * SA_NODE + cq * 2) = make_uint2(h0, h1);
            *(uint2*)(Alo + r * SA_NODE + cq * 2) = make_uint2(l0, l1);
        }
    }
    __syncthreads();

    float acc[2][8][4];
    #pragma unroll
    for (int mt = 0; mt < 2; mt++)
        #pragma unroll
        for (int t = 0; t < 8; t++)
            #pragma unroll
            for (int j = 0; j < 4; j++) acc[mt][t][j] = 0.f;

    if (LAYER) gemm_tile_ldm<128, SA_LAYER>(Ahi, Alo, frag1, FragS, tid, rowgrp, colgrp, lane, acc);
    else       gemm_tile_ldm<K1,  SA_NODE >(Ahi, Alo, frag1, FragS, tid, rowgrp, colgrp, lane, acc);
    __syncthreads();

    // intermediate: relu(acc + b1), split once -> packed hi/lo
    #pragma unroll
    for (int mt = 0; mt < 2; mt++) {
        #pragma unroll
        for (int t = 0; t < 8; t++) {
            int col = (colgrp * 8 + t) * 8 + 2 * (lane & 3);
            float bb0 = __ldg(b1 + col), bb1 = __ldg(b1 + col + 1);
            int r0 = rowgrp * 32 + mt * 16 + (lane >> 2);
            float z00 = fmaxf(acc[mt][t][0] + bb0, 0.f);
            float z01 = fmaxf(acc[mt][t][1] + bb1, 0.f);
            float z10 = fmaxf(acc[mt][t][2] + bb0, 0.f);
            float z11 = fmaxf(acc[mt][t][3] + bb1, 0.f);
            unsigned h, l;
            bf16_split2(z00, z01, h, l);
            Ahi[r0 * SA_LAYER + col / 2] = h;
            Alo[r0 * SA_LAYER + col / 2] = l;
            bf16_split2(z10, z11, h, l);
            Ahi[(r0 + 8) * SA_LAYER + col / 2] = h;
            Alo[(r0 + 8) * SA_LAYER + col / 2] = l;
        }
    }
    __syncthreads();

    #pragma unroll
    for (int mt = 0; mt < 2; mt++)
        #pragma unroll
        for (int t = 0; t < 8; t++)
            #pragma unroll
            for (int j = 0; j < 4; j++) acc[mt][t][j] = 0.f;

    gemm_tile_ldm<128, SA_LAYER>(Ahi, Alo, frag2, FragS, tid, rowgrp, colgrp, lane, acc);

    // epilogue: Hout = relu(bn(gemm2 + b2)) + h_in  (h_in re-read from A, L2-hot)
    #pragma unroll
    for (int mt = 0; mt < 2; mt++) {
        #pragma unroll
        for (int t = 0; t < 8; t++) {
            int col = (colgrp * 8 + t) * 8 + 2 * (lane & 3);
            float bb0 = __ldg(b2 + col), bb1 = __ldg(b2 + col + 1);
            int r0 = rowgrp * 32 + mt * 16 + (lane >> 2);
            if (LAYER) {
                float gm0 = __ldg(gamma + col) * bnscale, gm1 = __ldg(gamma + col + 1) * bnscale;
                float bt0 = __ldg(beta + col), bt1 = __ldg(beta + col + 1);
                #pragma unroll
                for (int half = 0; half < 2; half++) {
                    int row = n0 + r0 + 8 * half;
                    if (row < N) {
                        float z0 = fmaxf((acc[mt][t][2 * half + 0] + bb0) * gm0 + bt0, 0.f);
                        float z1 = fmaxf((acc[mt][t][2 * half + 1] + bb1) * gm1 + bt1, 0.f);
                        float2 hv = *(const float2*)(A + (size_t)row * 128 + col);
                        float2 o;
                        o.x = hv.x + z0; o.y = hv.y + z1;
                        *(float2*)(Hout + (size_t)row * 128 + col) = o;
                    }
                }
            } else {
                #pragma unroll
                for (int half = 0; half < 2; half++) {
                    int row = n0 + r0 + 8 * half;
                    if (row < N) {
                        float2 o;
                        o.x = acc[mt][t][2 * half + 0] + bb0;
                        o.y = acc[mt][t][2 * half + 1] + bb1;
                        *(float2*)(Hout + (size_t)row * 128 + col) = o;
                    }
                }
            }
        }
    }
}

// ---------------- edge-type table ----------------
__global__ void etab_kernel(const float* __restrict__ te, const float* __restrict__ de,
                            const float* __restrict__ lew, const float* __restrict__ leb)
{
    int l = blockIdx.x / 24, t = blockIdx.x % 24;
    int bt = t / 4, bd = t % 4;
    int c = threadIdx.x;
    float s = leb[l * 128 + c];
    #pragma unroll 4
    for (int k = 0; k < 64; k++) {
        float ev = te[bt * 64 + k] + de[bd * 64 + k];
        s += ev * __ldg(lew + (size_t)(l * 64 + k) * 128 + c);
    }
    g_etab[(l * 24 + t) * 128 + c] = s;
}

// ---------------- CSR build by dst (counting sort) ----------------
__global__ void deg_zero_kernel(int N)
{
    int i = blockIdx.x * blockDim.x + threadIdx.x;
    if (i < N) g_deg[i] = 0;
}
__global__ void deg_count_kernel(const int* __restrict__ ei, int E)
{
    int e = blockIdx.x * blockDim.x + threadIdx.x;
    if (e < E) atomicAdd(&g_deg[ei[E + e]], 1);   // by dst
}
__global__ void scan1_kernel(int N)
{
    __shared__ int s[1024];
    int i = blockIdx.x * 1024 + threadIdx.x;
    int v = (i < N) ? g_deg[i] : 0;
    s[threadIdx.x] = v;
    __syncthreads();
    #pragma unroll
    for (int off = 1; off < 1024; off <<= 1) {
        int t = (threadIdx.x >= off) ? s[threadIdx.x - off] : 0;
        __syncthreads();
        s[threadIdx.x] += t;
        __syncthreads();
    }
    if (i < N) g_rowincl[i] = s[threadIdx.x];
    if (threadIdx.x == 1023) g_part[blockIdx.x] = s[1023];
}
__global__ void scan2_kernel(int nblk)
{
    if (threadIdx.x == 0) {
        int run = 0;
        for (int b = 0; b < nblk; b++) {
            int t = g_part[b];
            g_part[b] = run;
            run += t;
        }
    }
}
__global__ void scan3_kernel(int N, int E)
{
    int i = blockIdx.x * blockDim.x + threadIdx.x;
    if (i < N) {
        int excl = g_rowincl[i] - g_deg[i] + g_part[i >> 10];
        g_rowoff[i] = excl;
        g_cur[i] = excl;
    }
    if (i == 0) g_rowoff[N] = E;
}
__global__ void place_kernel(const int* __restrict__ ei, const int* __restrict__ ea, int E)
{
    int e = blockIdx.x * blockDim.x + threadIdx.x;
    if (e >= E) return;
    int src = ei[e], dst = ei[E + e];
    int bt = ea[2 * e], bd = ea[2 * e + 1];
    bt = min(max(bt, 0), 5);
    bd = min(max(bd, 0), 3);
    int pos = atomicAdd(&g_cur[dst], 1);
    g_edt[pos] = (unsigned)src | ((unsigned)(bt * 4 + bd) << 20);
}

// ---------------- segmented pooling ----------------
__global__ void pool_seg_kernel(const float* __restrict__ h, int npg, float* __restrict__ out_ge)
{
    int g = blockIdx.x, c = threadIdx.x;
    const float* p = h + (size_t)g * npg * 128 + c;
    float s = 0.f, m = -INFINITY;
    for (int i = 0; i < npg; i++) {
        float v = p[(size_t)i * 128];
        s += v;
        m = fmaxf(m, v);
    }
    float mean = s / (float)npg;
    g_gemb[g * 256 + c] = mean;
    g_gemb[g * 256 + 128 + c] = m;
    out_ge[g * 256 + c] = mean;
    out_ge[g * 256 + 128 + c] = m;
}

// ---------------- small dense layers: 8 graphs/thread for W reuse ----------------
__global__ void dense_relu_kernel(const float* __restrict__ X, const float* __restrict__ W,
                                  const float* __restrict__ b, float* __restrict__ Y,
                                  int G, int K, int C)
{
    int C4 = C >> 2;
    int ng = (G + 7) / 8;
    int idx = blockIdx.x * blockDim.x + threadIdx.x;
    if (idx >= ng * C4) return;
    int gb = (idx / C4) * 8;
    int c  = (idx % C4) * 4;
    int gcnt = min(8, G - gb);
    float4 bb = *(const float4*)(b + c);
    float4 s[8];
    #pragma unroll
    for (int j = 0; j < 8; j++) s[j] = bb;
    for (int k = 0; k < K; k++) {
        float4 w = *(const float4*)(W + (size_t)k * C + c);
        #pragma unroll
        for (int j = 0; j < 8; j++) {
            if (j < gcnt) {
                float xv = __ldg(X + (size_t)(gb + j) * K + k);
                s[j].x += xv * w.x; s[j].y += xv * w.y;
                s[j].z += xv * w.z; s[j].w += xv * w.w;
            }
        }
    }
    #pragma unroll
    for (int j = 0; j < 8; j++) {
        if (j < gcnt) {
            float4 o;
            o.x = fmaxf(s[j].x, 0.f); o.y = fmaxf(s[j].y, 0.f);
            o.z = fmaxf(s[j].z, 0.f); o.w = fmaxf(s[j].w, 0.f);
            *(float4*)(Y + (size_t)(gb + j) * C + c) = o;
        }
    }
}

__global__ void comb_kernel(int G, float* __restrict__ out_comb)
{
    int idx = blockIdx.x * blockDim.x + threadIdx.x;
    if (idx >= G * 384) return;
    int g = idx / 384, c = idx % 384;
    float v = (c < 256) ? g_gemb[g * 256 + c] : g_ex2[g * 128 + (c - 256)];
    g_comb[idx] = v;
    out_comb[idx] = v;
}

__global__ void head3_kernel(int G, const float* __restrict__ hw3,
                             const float* __restrict__ hb3, float* __restrict__ out)
{
    int g = blockIdx.x * blockDim.x + threadIdx.x;
    if (g >= G) return;
    float s = __ldg(hb3);
    #pragma unroll 4
    for (int k = 0; k < 128; k++)
        s += g_o2[g * 128 + k] * __ldg(hw3 + k);
    out[g] = s;
}

// ---------------- launch ----------------
extern "C" void kernel_launch(void* const* d_in, const int* in_sizes, int n_in,
                              void* d_out, int out_size)
{
    const float* x     = (const float*)d_in[0];
    const int*   ei    = (const int*)d_in[1];
    const int*   ea    = (const int*)d_in[2];
    const float* expf_ = (const float*)d_in[4];
    const float* nw1 = (const float*)d_in[5];
    const float* nb1 = (const float*)d_in[6];
    const float* nw2 = (const float*)d_in[7];
    const float* nb2 = (const float*)d_in[8];
    const float* te  = (const float*)d_in[9];
    const float* de  = (const float*)d_in[10];
    const float* lew = (const float*)d_in[11];
    const float* leb = (const float*)d_in[12];
    const float* mw1 = (const float*)d_in[13];
    const float* mb1 = (const float*)d_in[14];
    const float* mw2 = (const float*)d_in[15];
    const float* mb2 = (const float*)d_in[16];
    const float* gamma = (const float*)d_in[17];
    const float* beta  = (const float*)d_in[18];
    const float* ew1 = (const float*)d_in[19];
    const float* eb1 = (const float*)d_in[20];
    const float* ew2 = (const float*)d_in[21];
    const float* eb2 = (const float*)d_in[22];
    const float* hw1 = (const float*)d_in[23];
    const float* hb1 = (const float*)d_in[24];
    const float* hw2 = (const float*)d_in[25];
    const float* hb2 = (const float*)d_in[26];
    const float* hw3 = (const float*)d_in[27];
    const float* hb3 = (const float*)d_in[28];

    const int N = in_sizes[0] / 32;
    const int E = in_sizes[1] / 2;
    const int G = in_sizes[4] / 200;
    const int npg = N / G;
    const float bnscale = 1.0f / sqrtf(1.0f + 1e-5f);

    float*    p_h0;    cudaGetSymbolAddress((void**)&p_h0, g_h);
    float*    p_h1;    cudaGetSymbolAddress((void**)&p_h1, g_hb);
    float*    p_etab;  cudaGetSymbolAddress((void**)&p_etab, g_etab);
    unsigned* p_wf;    cudaGetSymbolAddress((void**)&p_wf, g_wfrag);
    int*      p_roff;  cudaGetSymbolAddress((void**)&p_roff, g_rowoff);
    unsigned* p_edt;   cudaGetSymbolAddress((void**)&p_edt, g_edt);
    float*    p_ex1;   cudaGetSymbolAddress((void**)&p_ex1, g_ex1);
    float*    p_ex2;   cudaGetSymbolAddress((void**)&p_ex2, g_ex2);
    float*    p_comb;  cudaGetSymbolAddress((void**)&p_comb, g_comb);
    float*    p_o1;    cudaGetSymbolAddress((void**)&p_o1, g_o1);
    float*    p_o2;    cudaGetSymbolAddress((void**)&p_o2, g_o2);

    const size_t OFF_N1 = 0;
    const size_t OFF_N2 = 4096;
    const size_t BASE_L = 20480;
    const size_t SZ128  = 16384;

    auto kNode  = mlp2_mma_kernel<32, false>;
    auto kLayer = mlp2_mma_kernel<128, true>;
    const int SMEM = (2 * 128 * SA_LAYER + 4096) * 4;   // 86016 B
    cudaFuncSetAttribute((const void*)kNode,  cudaFuncAttributeMaxDynamicSharedMemorySize, SMEM);
    cudaFuncSetAttribute((const void*)kLayer, cudaFuncAttributeMaxDynamicSharedMemorySize, SMEM);

    const int nb = (N + 127) / 128;

    // weight fragment tables (batched over layers via blockIdx.z)
    wfrag_batch_kernel<<<dim3(8, 16, LLAYERS), 32>>>(mw1, p_wf + BASE_L, 16384, 2 * (int)SZ128);
    wfrag_batch_kernel<<<dim3(8, 16, LLAYERS), 32>>>(mw2, p_wf + BASE_L + SZ128, 16384, 2 * (int)SZ128);
    wfrag_batch_kernel<<<dim3(2, 16, 1), 32>>>(nw1, p_wf + OFF_N1, 0, 0);
    wfrag_batch_kernel<<<dim3(8, 16, 1), 32>>>(nw2, p_wf + OFF_N2, 0, 0);
    // edge-type tables
    etab_kernel<<<LLAYERS * 24, 128>>>(te, de, lew, leb);
    // node projection MLP -> h0
    kNode<<<nb, 256, SMEM>>>(x, N, p_wf + OFF_N1, nb1, p_wf + OFF_N2, nb2,
                             nullptr, nullptr, 1.f, p_h0, nullptr, nullptr, nullptr);

    // CSR build (edges sorted by dst) — independent of kNode
    const int nscan = (N + 1023) / 1024;
    deg_zero_kernel<<<(N + 255) / 256, 256>>>(N);
    deg_count_kernel<<<(E + 255) / 256, 256>>>(ei, E);
    scan1_kernel<<<nscan, 1024>>>(N);
    scan2_kernel<<<1, 32>>>(nscan);
    scan3_kernel<<<(N + 255) / 256, 256>>>(N, E);
    place_kernel<<<(E + 255) / 256, 256>>>(ei, ea, E);

    float* hb[2] = {p_h0, p_h1};

    // GINE layers: ping-pong h buffers; staged gather fused into load
    for (int l = 0; l < LLAYERS; l++) {
        kLayer<<<nb, 256, SMEM>>>(hb[l & 1], N,
                                  p_wf + BASE_L + (size_t)(2 * l) * SZ128, mb1 + l * 128,
                                  p_wf + BASE_L + (size_t)(2 * l + 1) * SZ128, mb2 + l * 128,
                                  gamma + l * 128, beta + l * 128, bnscale, hb[(l + 1) & 1],
                                  p_etab + (size_t)l * 24 * 128, p_roff, p_edt);
    }
    float* p_hfin = hb[LLAYERS & 1];

    // readout + heads
    float* out_f    = (float*)d_out;
    float* out_ge   = out_f + G;              // graph_emb [G,256]
    float* out_comb = out_f + G + G * 256;    // combined  [G,384]

    pool_seg_kernel<<<G, 128>>>(p_hfin, npg, out_ge);

    {
        int ng = (G + 7) / 8;
        dense_relu_kernel<<<(ng * 32 + 255) / 256, 256>>>(expf_, ew1, eb1, p_ex1, G, 200, 128);
        dense_relu_kernel<<<(ng * 32 + 255) / 256, 256>>>(p_ex1, ew2, eb2, p_ex2, G, 128, 128);
        comb_kernel<<<(G * 384 + 255) / 256, 256>>>(G, out_comb);
        dense_relu_kernel<<<(ng * 64 + 255) / 256, 256>>>(p_comb, hw1, hb1, p_o1, G, 384, 256);
        dense_relu_kernel<<<(ng * 32 + 255) / 256, 256>>>(p_o1, hw2, hb2, p_o2, G, 256, 128);
    }
    head3_kernel<<<(G + 127) / 128, 128>>>(G, hw3, hb3, out_f);
}

// round 16
// speedup vs baseline: 1.4795x; 1.4795x over previous
#include <cuda_runtime.h>
#include <math.h>

#define HDIM 128
#define LLAYERS 5
#define NMAX 100000
#define EMAX 200000
#define GMAX 2000

// packed (bf16x2) smem strides in u32 units
#define SA_LAYER 68   // 64 data + 4 pad
#define SA_NODE  20   // 16 data + 4 pad

// ---------------- scratch (static device globals; no allocation) ----------------
__device__ float    g_h[NMAX * HDIM];     // h ping
__device__ float    g_hb[NMAX * HDIM];    // h pong
__device__ float    g_etab[LLAYERS * 24 * HDIM];
__device__ __align__(16) unsigned g_wfrag[368640];   // bf16 hi/lo weight fragments
// CSR-by-dst scratch
__device__ int      g_deg[NMAX];
__device__ int      g_rowincl[NMAX];
__device__ int      g_rowoff[NMAX + 1];
__device__ int      g_cur[NMAX];
__device__ int      g_part[256];
__device__ unsigned g_edt[EMAX];          // src | type<<20
// head scratch
__device__ float    g_gemb[GMAX * 256];
__device__ float    g_ex1[GMAX * HDIM];
__device__ float    g_ex2[GMAX * HDIM];
__device__ float    g_comb[GMAX * 384];
__device__ float    g_o1[GMAX * 256];
__device__ float    g_o2[GMAX * 128];

// ---------------- helpers ----------------
__device__ __forceinline__ void bf16_split2(float x, float y, unsigned& hi, unsigned& lo) {
    asm("cvt.rn.bf16x2.f32 %0, %1, %2;" : "=r"(hi) : "f"(y), "f"(x));
    float hx = __uint_as_float(hi << 16);
    float hy = __uint_as_float(hi & 0xffff0000u);
    float lx = x - hx, ly = y - hy;
    asm("cvt.rn.bf16x2.f32 %0, %1, %2;" : "=r"(lo) : "f"(ly), "f"(lx));
}
__device__ __forceinline__ void mma_bf16(float c[4], const unsigned a[4],
                                         unsigned b0, unsigned b1) {
    asm volatile(
        "mma.sync.aligned.m16n8k16.row.col.f32.bf16.bf16.f32 "
        "{%0,%1,%2,%3}, {%4,%5,%6,%7}, {%8,%9}, {%0,%1,%2,%3};"
        : "+f"(c[0]), "+f"(c[1]), "+f"(c[2]), "+f"(c[3])
        : "r"(a[0]), "r"(a[1]), "r"(a[2]), "r"(a[3]), "r"(b0), "r"(b1));
}
__device__ __forceinline__ unsigned smaddr(const void* p) {
    return (unsigned)__cvta_generic_to_shared(p);
}
__device__ __forceinline__ void ldsm_x4(unsigned a[4], unsigned addr) {
    asm volatile("ldmatrix.sync.aligned.m8n8.x4.shared.b16 {%0,%1,%2,%3}, [%4];"
                 : "=r"(a[0]), "=r"(a[1]), "=r"(a[2]), "=r"(a[3]) : "r"(addr));
}

// ---------------- weight fragment precompute (bf16 hi/lo split, batched) --------
__global__ void wfrag_batch_kernel(const float* __restrict__ W, unsigned* __restrict__ out,
                                   int wstride, int ostride)
{
    const float* Wm = W + (size_t)blockIdx.z * wstride;
    unsigned* om = out + (size_t)blockIdx.z * ostride;
    int ks = blockIdx.x, nt = blockIdx.y, lane = threadIdx.x;
    int n  = nt * 8 + (lane >> 2);
    int k0 = ks * 16 + (lane & 3) * 2;
    float w00 = Wm[k0 * 128 + n];
    float w01 = Wm[(k0 + 1) * 128 + n];
    float w10 = Wm[(k0 + 8) * 128 + n];
    float w11 = Wm[(k0 + 9) * 128 + n];
    unsigned bh0, bl0, bh1, bl1;
    bf16_split2(w00, w01, bh0, bl0);
    bf16_split2(w10, w11, bh1, bl1);
    unsigned* p = om + ((size_t)(ks * 16 + nt) * 32 + lane) * 4;
    p[0] = bh0; p[1] = bh1; p[2] = bl0; p[3] = bl1;
}

// ---------------- 3x-bf16 tile GEMM: ldmatrix A + cp.async-staged B frags -------
template <int K, int SA>
__device__ __forceinline__ void gemm_tile_ldm(const unsigned* Ahi, const unsigned* Alo,
                                              const unsigned* __restrict__ frag,
                                              unsigned* FragS, int tid,
                                              int rowgrp, int colgrp, int lane,
                                              float acc[2][8][4])
{
    const int NKS = K / 16;
    const int lrow = lane & 15;
    const int lcol = (lane >> 4) * 4;

    // preload ks=0 fragment chunk (8KB = 256 threads x 2 x 16B)
    {
        unsigned daddr = smaddr(FragS) + tid * 16;
        const unsigned* src = frag + tid * 4;
        asm volatile(
            "cp.async.ca.shared.global [%0], [%1], 16;\n\t"
            "cp.async.ca.shared.global [%2], [%3], 16;\n\t"
            "cp.async.commit_group;"
            :: "r"(daddr), "l"(src), "r"(daddr + 4096), "l"(src + 1024) : "memory");
    }

    #pragma unroll
    for (int ks = 0; ks < NKS; ks++) {
        const unsigned* cur = FragS + (ks & 1) * 2048;
        asm volatile("cp.async.wait_group 0;" ::: "memory");
        __syncthreads();
        if (ks + 1 < NKS) {
            unsigned daddr = smaddr(FragS + ((ks + 1) & 1) * 2048) + tid * 16;
            const unsigned* src = frag + (size_t)(ks + 1) * 2048 + tid * 4;
            asm volatile(
                "cp.async.ca.shared.global [%0], [%1], 16;\n\t"
                "cp.async.ca.shared.global [%2], [%3], 16;\n\t"
                "cp.async.commit_group;"
                :: "r"(daddr), "l"(src), "r"(daddr + 4096), "l"(src + 1024) : "memory");
        }
        unsigned ahi[2][4], alo[2][4];
        #pragma unroll
        for (int mt = 0; mt < 2; mt++) {
            int row = rowgrp * 32 + mt * 16 + lrow;
            unsigned off = 4u * (row * SA + ks * 8 + lcol);
            ldsm_x4(ahi[mt], smaddr(Ahi) + off);
            ldsm_x4(alo[mt], smaddr(Alo) + off);
        }
        #pragma unroll
        for (int t = 0; t < 8; t++) {
            const uint4 bf = *(const uint4*)(cur + ((colgrp * 8 + t) * 32 + lane) * 4);
            #pragma unroll
            for (int mt = 0; mt < 2; mt++) {
                mma_bf16(acc[mt][t], ahi[mt], bf.x, bf.y);   // hi*hi
                mma_bf16(acc[mt][t], ahi[mt], bf.z, bf.w);   // hi*lo
                mma_bf16(acc[mt][t], alo[mt], bf.x, bf.y);   // lo*hi
            }
        }
    }
}

// ---------------- fused gather + 2-GEMM MLP ----------------
// LAYER=true : A_in[r] = A[r] + sum_{e in CSR[r]} relu(A[src_e] + etab[type_e]);
//              Hout[r] = relu(bn(mlp(A_in))) + A[r]
// LAYER=false: Hout[r] = mlp(A)   (A = x, K1=32)
template <int K1, bool LAYER>
__global__ __launch_bounds__(256, 2)
void mlp2_mma_kernel(const float* __restrict__ A, int N,
                     const unsigned* __restrict__ frag1, const float* __restrict__ b1,
                     const unsigned* __restrict__ frag2, const float* __restrict__ b2,
                     const float* __restrict__ gamma, const float* __restrict__ beta,
                     float bnscale, float* __restrict__ Hout,
                     const float* __restrict__ etab_l,
                     const int* __restrict__ rowoff, const unsigned* __restrict__ edt)
{
    extern __shared__ unsigned smu[];
    unsigned* Ahi   = smu;
    unsigned* Alo   = smu + 128 * SA_LAYER;
    unsigned* FragS = smu + 2 * 128 * SA_LAYER;   // 4096 u32 double buffer
    const int tid = threadIdx.x, lane = tid & 31, warp = tid >> 5;
    const int rowgrp = warp >> 1, colgrp = warp & 1;
    const int n0 = blockIdx.x * 128;

    if (LAYER) {
        // gather + load: warp per row; lane covers cols lane*4..lane*4+3
        for (int r = warp; r < 128; r += 8) {
            int row = n0 + r;
            float4 a = make_float4(0.f, 0.f, 0.f, 0.f);
            if (row < N) {
                a = *(const float4*)(A + (size_t)row * 128 + lane * 4);
                int e0 = __ldg(rowoff + row), e1 = __ldg(rowoff + row + 1);
                for (int e = e0; e < e1; e++) {
                    unsigned pk = __ldg(edt + e);
                    const float* hv = A + (size_t)(pk & 0xFFFFF) * 128;
                    const float* et = etab_l + (pk >> 20) * 128;
                    float4 h4 = *(const float4*)(hv + lane * 4);
                    float4 e4 = *(const float4*)(et + lane * 4);
                    a.x += fmaxf(h4.x + e4.x, 0.f);
                    a.y += fmaxf(h4.y + e4.y, 0.f);
                    a.z += fmaxf(h4.z + e4.z, 0.f);
                    a.w += fmaxf(h4.w + e4.w, 0.f);
                }
            }
            unsigned h0, l0, h1, l1;
            bf16_split2(a.x, a.y, h0, l0);
            bf16_split2(a.z, a.w, h1, l1);
            *(uint2*)(Ahi + r * SA_LAYER + lane * 2) = make_uint2(h0, h1);
            *(uint2*)(Alo + r * SA_LAYER + lane * 2) = make_uint2(l0, l1);
        }
    } else {
        const int QK = K1 / 4;
        #pragma unroll
        for (int i = 0; i < (128 * QK) / 256; i++) {
            int idx = tid + i * 256;
            int r = idx / QK, cq = idx % QK;
            float4 v = make_float4(0.f, 0.f, 0.f, 0.f);
            if (n0 + r < N)
                v = *(const float4*)(A + (size_t)(n0 + r) * K1 + cq * 4);
            unsigned h0, l0, h1, l1;
            bf16_split2(v.x, v.y, h0, l0);
            bf16_split2(v.z, v.w, h1, l1);
            *(uint2*)(Ahi + r * SA_NODE + cq * 2) = make_uint2(h0, h1);
            *(uint2*)(Alo + r * SA_NODE + cq * 2) = make_uint2(l0, l1);
        }
    }
    __syncthreads();

    float acc[2][8][4];
    #pragma unroll
    for (int mt = 0; mt < 2; mt++)
        #pragma unroll
        for (int t = 0; t < 8; t++)
            #pragma unroll
            for (int j = 0; j < 4; j++) acc[mt][t][j] = 0.f;

    if (LAYER) gemm_tile_ldm<128, SA_LAYER>(Ahi, Alo, frag1, FragS, tid, rowgrp, colgrp, lane, acc);
    else       gemm_tile_ldm<K1,  SA_NODE >(Ahi, Alo, frag1, FragS, tid, rowgrp, colgrp, lane, acc);
    __syncthreads();

    // intermediate: relu(acc + b1), split once -> packed hi/lo
    #pragma unroll
    for (int mt = 0; mt < 2; mt++) {
        #pragma unroll
        for (int t = 0; t < 8; t++) {
            int col = (colgrp * 8 + t) * 8 + 2 * (lane & 3);
            float bb0 = __ldg(b1 + col), bb1 = __ldg(b1 + col + 1);
            int r0 = rowgrp * 32 + mt * 16 + (lane >> 2);
            float z00 = fmaxf(acc[mt][t][0] + bb0, 0.f);
            float z01 = fmaxf(acc[mt][t][1] + bb1, 0.f);
            float z10 = fmaxf(acc[mt][t][2] + bb0, 0.f);
            float z11 = fmaxf(acc[mt][t][3] + bb1, 0.f);
            unsigned h, l;
            bf16_split2(z00, z01, h, l);
            Ahi[r0 * SA_LAYER + col / 2] = h;
            Alo[r0 * SA_LAYER + col / 2] = l;
            bf16_split2(z10, z11, h, l);
            Ahi[(r0 + 8) * SA_LAYER + col / 2] = h;
            Alo[(r0 + 8) * SA_LAYER + col / 2] = l;
        }
    }
    __syncthreads();

    #pragma unroll
    for (int mt = 0; mt < 2; mt++)
        #pragma unroll
        for (int t = 0; t < 8; t++)
            #pragma unroll
            for (int j = 0; j < 4; j++) acc[mt][t][j] = 0.f;

    gemm_tile_ldm<128, SA_LAYER>(Ahi, Alo, frag2, FragS, tid, rowgrp, colgrp, lane, acc);

    // epilogue: Hout = relu(bn(gemm2 + b2)) + h_in  (h_in re-read from A, L2-hot)
    #pragma unroll
    for (int mt = 0; mt < 2; mt++) {
        #pragma unroll
        for (int t = 0; t < 8; t++) {
            int col = (colgrp * 8 + t) * 8 + 2 * (lane & 3);
            float bb0 = __ldg(b2 + col), bb1 = __ldg(b2 + col + 1);
            int r0 = rowgrp * 32 + mt * 16 + (lane >> 2);
            if (LAYER) {
                float gm0 = __ldg(gamma + col) * bnscale, gm1 = __ldg(gamma + col + 1) * bnscale;
                float bt0 = __ldg(beta + col), bt1 = __ldg(beta + col + 1);
                #pragma unroll
                for (int half = 0; half < 2; half++) {
                    int row = n0 + r0 + 8 * half;
                    if (row < N) {
                        float z0 = fmaxf((acc[mt][t][2 * half + 0] + bb0) * gm0 + bt0, 0.f);
                        float z1 = fmaxf((acc[mt][t][2 * half + 1] + bb1) * gm1 + bt1, 0.f);
                        float2 hv = *(const float2*)(A + (size_t)row * 128 + col);
                        float2 o;
                        o.x = hv.x + z0; o.y = hv.y + z1;
                        *(float2*)(Hout + (size_t)row * 128 + col) = o;
                    }
                }
            } else {
                #pragma unroll
                for (int half = 0; half < 2; half++) {
                    int row = n0 + r0 + 8 * half;
                    if (row < N) {
                        float2 o;
                        o.x = acc[mt][t][2 * half + 0] + bb0;
                        o.y = acc[mt][t][2 * half + 1] + bb1;
                        *(float2*)(Hout + (size_t)row * 128 + col) = o;
                    }
                }
            }
        }
    }
}

// ---------------- edge-type table ----------------
__global__ void etab_kernel(const float* __restrict__ te, const float* __restrict__ de,
                            const float* __restrict__ lew, const float* __restrict__ leb)
{
    int l = blockIdx.x / 24, t = blockIdx.x % 24;
    int bt = t / 4, bd = t % 4;
    int c = threadIdx.x;
    float s = leb[l * 128 + c];
    #pragma unroll 4
    for (int k = 0; k < 64; k++) {
        float ev = te[bt * 64 + k] + de[bd * 64 + k];
        s += ev * __ldg(lew + (size_t)(l * 64 + k) * 128 + c);
    }
    g_etab[(l * 24 + t) * 128 + c] = s;
}

// ---------------- CSR build by dst (counting sort) ----------------
__global__ void deg_zero_kernel(int N)
{
    int i = blockIdx.x * blockDim.x + threadIdx.x;
    if (i < N) g_deg[i] = 0;
}
__global__ void deg_count_kernel(const int* __restrict__ ei, int E)
{
    int e = blockIdx.x * blockDim.x + threadIdx.x;
    if (e < E) atomicAdd(&g_deg[ei[E + e]], 1);   // by dst
}
__global__ void scan1_kernel(int N)
{
    __shared__ int s[1024];
    int i = blockIdx.x * 1024 + threadIdx.x;
    int v = (i < N) ? g_deg[i] : 0;
    s[threadIdx.x] = v;
    __syncthreads();
    #pragma unroll
    for (int off = 1; off < 1024; off <<= 1) {
        int t = (threadIdx.x >= off) ? s[threadIdx.x - off] : 0;
        __syncthreads();
        s[threadIdx.x] += t;
        __syncthreads();
    }
    if (i < N) g_rowincl[i] = s[threadIdx.x];
    if (threadIdx.x == 1023) g_part[blockIdx.x] = s[1023];
}
__global__ void scan2_kernel(int nblk)
{
    if (threadIdx.x == 0) {
        int run = 0;
        for (int b = 0; b < nblk; b++) {
            int t = g_part[b];
            g_part[b] = run;
            run += t;
        }
    }
}
__global__ void scan3_kernel(int N, int E)
{
    int i = blockIdx.x * blockDim.x + threadIdx.x;
    if (i < N) {
        int excl = g_rowincl[i] - g_deg[i] + g_part[i >> 10];
        g_rowoff[i] = excl;
        g_cur[i] = excl;
    }
    if (i == 0) g_rowoff[N] = E;
}
__global__ void place_kernel(const int* __restrict__ ei, const int* __restrict__ ea, int E)
{
    int e = blockIdx.x * blockDim.x + threadIdx.x;
    if (e >= E) return;
    int src = ei[e], dst = ei[E + e];
    int bt = ea[2 * e], bd = ea[2 * e + 1];
    bt = min(max(bt, 0), 5);
    bd = min(max(bd, 0), 3);
    int pos = atomicAdd(&g_cur[dst], 1);
    g_edt[pos] = (unsigned)src | ((unsigned)(bt * 4 + bd) << 20);
}

// ---------------- segmented pooling ----------------
__global__ void pool_seg_kernel(const float* __restrict__ h, int npg, float* __restrict__ out_ge)
{
    int g = blockIdx.x, c = threadIdx.x;
    const float* p = h + (size_t)g * npg * 128 + c;
    float s = 0.f, m = -INFINITY;
    for (int i = 0; i < npg; i++) {
        float v = p[(size_t)i * 128];
        s += v;
        m = fmaxf(m, v);
    }
    float mean = s / (float)npg;
    g_gemb[g * 256 + c] = mean;
    g_gemb[g * 256 + 128 + c] = m;
    out_ge[g * 256 + c] = mean;
    out_ge[g * 256 + 128 + c] = m;
}

// ---------------- tiled head GEMM: Y = relu(X @ W + b), 64x64 tile/block --------
__global__ __launch_bounds__(256)
void dense_tiled_kernel(const float* __restrict__ X, const float* __restrict__ W,
                        const float* __restrict__ b, float* __restrict__ Y,
                        int G, int K, int C)
{
    __shared__ float  Xs[64][33];
    __shared__ float4 Ws[32][16];
    const int tid = threadIdx.x;
    const int tx = tid & 15, ty = tid >> 4;
    const int cb = blockIdx.x * 64, gb = blockIdx.y * 64;

    float acc[4][4];
    #pragma unroll
    for (int i = 0; i < 4; i++)
        #pragma unroll
        for (int j = 0; j < 4; j++) acc[i][j] = 0.f;

    for (int k0 = 0; k0 < K; k0 += 32) {
        #pragma unroll 4
        for (int i = tid; i < 64 * 32; i += 256) {
            int r = i >> 5, c = i & 31;
            float v = 0.f;
            if (gb + r < G && k0 + c < K)
                v = __ldg(X + (size_t)(gb + r) * K + k0 + c);
            Xs[r][c] = v;
        }
        #pragma unroll 2
        for (int i = tid; i < 32 * 16; i += 256) {
            int r = i >> 4, c4 = i & 15;
            float4 v = make_float4(0.f, 0.f, 0.f, 0.f);
            if (k0 + r < K)
                v = *(const float4*)(W + (size_t)(k0 + r) * C + cb + c4 * 4);
            Ws[r][c4] = v;
        }
        __syncthreads();
        #pragma unroll 8
        for (int kk = 0; kk < 32; kk++) {
            float a0 = Xs[ty * 4 + 0][kk];
            float a1 = Xs[ty * 4 + 1][kk];
            float a2 = Xs[ty * 4 + 2][kk];
            float a3 = Xs[ty * 4 + 3][kk];
            float4 w = Ws[kk][tx];
            acc[0][0] += a0 * w.x; acc[0][1] += a0 * w.y; acc[0][2] += a0 * w.z; acc[0][3] += a0 * w.w;
            acc[1][0] += a1 * w.x; acc[1][1] += a1 * w.y; acc[1][2] += a1 * w.z; acc[1][3] += a1 * w.w;
            acc[2][0] += a2 * w.x; acc[2][1] += a2 * w.y; acc[2][2] += a2 * w.z; acc[2][3] += a2 * w.w;
            acc[3][0] += a3 * w.x; acc[3][1] += a3 * w.y; acc[3][2] += a3 * w.z; acc[3][3] += a3 * w.w;
        }
        __syncthreads();
    }

    float4 bb = *(const float4*)(b + cb + tx * 4);
    #pragma unroll
    for (int i = 0; i < 4; i++) {
        int row = gb + ty * 4 + i;
        if (row < G) {
            float4 o;
            o.x = fmaxf(acc[i][0] + bb.x, 0.f);
            o.y = fmaxf(acc[i][1] + bb.y, 0.f);
            o.z = fmaxf(acc[i][2] + bb.z, 0.f);
            o.w = fmaxf(acc[i][3] + bb.w, 0.f);
            *(float4*)(Y + (size_t)row * C + cb + tx * 4) = o;
        }
    }
}

__global__ void comb_kernel(int G, float* __restrict__ out_comb)
{
    int idx = blockIdx.x * blockDim.x + threadIdx.x;
    if (idx >= G * 384) return;
    int g = idx / 384, c = idx % 384;
    float v = (c < 256) ? g_gemb[g * 256 + c] : g_ex2[g * 128 + (c - 256)];
    g_comb[idx] = v;
    out_comb[idx] = v;
}

__global__ void head3_kernel(int G, const float* __restrict__ hw3,
                             const float* __restrict__ hb3, float* __restrict__ out)
{
    int g = blockIdx.x * blockDim.x + threadIdx.x;
    if (g >= G) return;
    float s = __ldg(hb3);
    #pragma unroll 4
    for (int k = 0; k < 128; k++)
        s += g_o2[g * 128 + k] * __ldg(hw3 + k);
    out[g] = s;
}

// ---------------- launch ----------------
extern "C" void kernel_launch(void* const* d_in, const int* in_sizes, int n_in,
                              void* d_out, int out_size)
{
    const float* x     = (const float*)d_in[0];
    const int*   ei    = (const int*)d_in[1];
    const int*   ea    = (const int*)d_in[2];
    const float* expf_ = (const float*)d_in[4];
    const float* nw1 = (const float*)d_in[5];
    const float* nb1 = (const float*)d_in[6];
    const float* nw2 = (const float*)d_in[7];
    const float* nb2 = (const float*)d_in[8];
    const float* te  = (const float*)d_in[9];
    const float* de  = (const float*)d_in[10];
    const float* lew = (const float*)d_in[11];
    const float* leb = (const float*)d_in[12];
    const float* mw1 = (const float*)d_in[13];
    const float* mb1 = (const float*)d_in[14];
    const float* mw2 = (const float*)d_in[15];
    const float* mb2 = (const float*)d_in[16];
    const float* gamma = (const float*)d_in[17];
    const float* beta  = (const float*)d_in[18];
    const float* ew1 = (const float*)d_in[19];
    const float* eb1 = (const float*)d_in[20];
    const float* ew2 = (const float*)d_in[21];
    const float* eb2 = (const float*)d_in[22];
    const float* hw1 = (const float*)d_in[23];
    const float* hb1 = (const float*)d_in[24];
    const float* hw2 = (const float*)d_in[25];
    const float* hb2 = (const float*)d_in[26];
    const float* hw3 = (const float*)d_in[27];
    const float* hb3 = (const float*)d_in[28];

    const int N = in_sizes[0] / 32;
    const int E = in_sizes[1] / 2;
    const int G = in_sizes[4] / 200;
    const int npg = N / G;
    const float bnscale = 1.0f / sqrtf(1.0f + 1e-5f);

    float*    p_h0;    cudaGetSymbolAddress((void**)&p_h0, g_h);
    float*    p_h1;    cudaGetSymbolAddress((void**)&p_h1, g_hb);
    float*    p_etab;  cudaGetSymbolAddress((void**)&p_etab, g_etab);
    unsigned* p_wf;    cudaGetSymbolAddress((void**)&p_wf, g_wfrag);
    int*      p_roff;  cudaGetSymbolAddress((void**)&p_roff, g_rowoff);
    unsigned* p_edt;   cudaGetSymbolAddress((void**)&p_edt, g_edt);
    float*    p_ex1;   cudaGetSymbolAddress((void**)&p_ex1, g_ex1);
    float*    p_ex2;   cudaGetSymbolAddress((void**)&p_ex2, g_ex2);
    float*    p_comb;  cudaGetSymbolAddress((void**)&p_comb, g_comb);
    float*    p_o1;    cudaGetSymbolAddress((void**)&p_o1, g_o1);
    float*    p_o2;    cudaGetSymbolAddress((void**)&p_o2, g_o2);

    const size_t OFF_N1 = 0;
    const size_t OFF_N2 = 4096;
    const size_t BASE_L = 20480;
    const size_t SZ128  = 16384;

    auto kNode  = mlp2_mma_kernel<32, false>;
    auto kLayer = mlp2_mma_kernel<128, true>;
    const int SMEM = (2 * 128 * SA_LAYER + 4096) * 4;   // 86016 B
    cudaFuncSetAttribute((const void*)kNode,  cudaFuncAttributeMaxDynamicSharedMemorySize, SMEM);
    cudaFuncSetAttribute((const void*)kLayer, cudaFuncAttributeMaxDynamicSharedMemorySize, SMEM);

    const int nb = (N + 127) / 128;

    // weight fragment tables (batched over layers via blockIdx.z)
    wfrag_batch_kernel<<<dim3(8, 16, LLAYERS), 32>>>(mw1, p_wf + BASE_L, 16384, 2 * (int)SZ128);
    wfrag_batch_kernel<<<dim3(8, 16, LLAYERS), 32>>>(mw2, p_wf + BASE_L + SZ128, 16384, 2 * (int)SZ128);
    wfrag_batch_kernel<<<dim3(2, 16, 1), 32>>>(nw1, p_wf + OFF_N1, 0, 0);
    wfrag_batch_kernel<<<dim3(8, 16, 1), 32>>>(nw2, p_wf + OFF_N2, 0, 0);
    // edge-type tables
    etab_kernel<<<LLAYERS * 24, 128>>>(te, de, lew, leb);
    // node projection MLP -> h0
    kNode<<<nb, 256, SMEM>>>(x, N, p_wf + OFF_N1, nb1, p_wf + OFF_N2, nb2,
                             nullptr, nullptr, 1.f, p_h0, nullptr, nullptr, nullptr);

    // CSR build (edges sorted by dst) — independent of kNode
    const int nscan = (N + 1023) / 1024;
    deg_zero_kernel<<<(N + 255) / 256, 256>>>(N);
    deg_count_kernel<<<(E + 255) / 256, 256>>>(ei, E);
    scan1_kernel<<<nscan, 1024>>>(N);
    scan2_kernel<<<1, 32>>>(nscan);
    scan3_kernel<<<(N + 255) / 256, 256>>>(N, E);
    place_kernel<<<(E + 255) / 256, 256>>>(ei, ea, E);

    float* hb[2] = {p_h0, p_h1};

    // GINE layers: ping-pong h buffers; gather aggregation fused into load
    for (int l = 0; l < LLAYERS; l++) {
        kLayer<<<nb, 256, SMEM>>>(hb[l & 1], N,
                                  p_wf + BASE_L + (size_t)(2 * l) * SZ128, mb1 + l * 128,
                                  p_wf + BASE_L + (size_t)(2 * l + 1) * SZ128, mb2 + l * 128,
                                  gamma + l * 128, beta + l * 128, bnscale, hb[(l + 1) & 1],
                                  p_etab + (size_t)l * 24 * 128, p_roff, p_edt);
    }
    float* p_hfin = hb[LLAYERS & 1];

    // readout + heads
    float* out_f    = (float*)d_out;
    float* out_ge   = out_f + G;              // graph_emb [G,256]
    float* out_comb = out_f + G + G * 256;    // combined  [G,384]

    pool_seg_kernel<<<G, 128>>>(p_hfin, npg, out_ge);

    {
        const int gy = (G + 63) / 64;
        dense_tiled_kernel<<<dim3(2, gy), 256>>>(expf_, ew1, eb1, p_ex1, G, 200, 128);
        dense_tiled_kernel<<<dim3(2, gy), 256>>>(p_ex1, ew2, eb2, p_ex2, G, 128, 128);
        comb_kernel<<<(G * 384 + 255) / 256, 256>>>(G, out_comb);
        dense_tiled_kernel<<<dim3(4, gy), 256>>>(p_comb, hw1, hb1, p_o1, G, 384, 256);
        dense_tiled_kernel<<<dim3(2, gy), 256>>>(p_o1, hw2, hb2, p_o2, G, 256, 128);
    }
    head3_kernel<<<(G + 127) / 128, 128>>>(G, hw3, hb3, out_f);
}